// round 1
// baseline (speedup 1.0000x reference)
#include <cuda_runtime.h>
#include <math.h>

#define NB 256
#define NJ 10
#define NI 1152
#define NP 16
#define NQ 8
#define NCH 9          // i-chunks for routing kernel
#define CH 128         // i per chunk

// Scratch (device globals — no allocation in kernel_launch).
__device__ float g_hat[(size_t)NB * NJ * NI * NP];       // [b][j][i][p], 188.7 MB
__device__ float g_spart[NCH * NB * NJ * NP];            // per-chunk s partials
__device__ float g_out0[NB * NJ * NP];
__device__ float g_outsum[NB * NJ * NP];

// ---------------------------------------------------------------------------
// K1: hat[b,j,i,p] = sum_q W[j,i,p,q] * in[b,i,q]
// grid (ic=18, j=10, bc=4), block 256. Thread owns (i, p-quad): W in registers,
// reused across 64 b. Inputs staged via SMEM in groups of 8 b.
// ---------------------------------------------------------------------------
__global__ __launch_bounds__(256) void k_hat(const float* __restrict__ in,
                                             const float* __restrict__ W) {
    const int ic = blockIdx.x;          // 0..17  (64 i each)
    const int j  = blockIdx.y;          // 0..9
    const int bc = blockIdx.z;          // 0..3   (64 b each)
    const int t  = threadIdx.x;
    const int p4 = t & 3;               // which p-quad
    const int il = t >> 2;              // 0..63
    const int i  = ic * 64 + il;

    // Load this thread's 4x8 W slice once (contiguous 128 B).
    float w[4][8];
    {
        const float4* Wv = (const float4*)(W + ((size_t)(j * NI + i) * NP + p4 * 4) * NQ);
        #pragma unroll
        for (int pp = 0; pp < 4; pp++) {
            float4 a = Wv[pp * 2], c = Wv[pp * 2 + 1];
            w[pp][0] = a.x; w[pp][1] = a.y; w[pp][2] = a.z; w[pp][3] = a.w;
            w[pp][4] = c.x; w[pp][5] = c.y; w[pp][6] = c.z; w[pp][7] = c.w;
        }
    }

    __shared__ float in_s[8 * 64 * NQ];   // 4096 floats = 16 KB

    for (int g = 0; g < 8; g++) {
        const int b0 = bc * 64 + g * 8;
        __syncthreads();
        #pragma unroll
        for (int k = 0; k < 4; k++) {
            int m   = t + 256 * k;        // float4 index 0..1023
            int bo  = m >> 7;             // 128 float4 per b
            int pos = m & 127;
            ((float4*)in_s)[m] =
                ((const float4*)(in + ((size_t)(b0 + bo) * NI + ic * 64) * NQ))[pos];
        }
        __syncthreads();
        #pragma unroll
        for (int bb = 0; bb < 8; bb++) {
            const int b = b0 + bb;
            const float* xs = in_s + (bb * 64 + il) * NQ;
            float x0 = xs[0], x1 = xs[1], x2 = xs[2], x3 = xs[3];
            float x4 = xs[4], x5 = xs[5], x6 = xs[6], x7 = xs[7];
            float r[4];
            #pragma unroll
            for (int pp = 0; pp < 4; pp++) {
                r[pp] = w[pp][0] * x0 + w[pp][1] * x1 + w[pp][2] * x2 + w[pp][3] * x3
                      + w[pp][4] * x4 + w[pp][5] * x5 + w[pp][6] * x6 + w[pp][7] * x7;
            }
            float4 acc; acc.x = r[0]; acc.y = r[1]; acc.z = r[2]; acc.w = r[3];
            *(float4*)(g_hat + ((size_t)(b * NJ + j) * NI + i) * NP + p4 * 4) = acc;
        }
    }
}

// ---------------------------------------------------------------------------
// K2: s0 = 0.1 * sum_i hat[b,j,i,:], then out0 = squash(s0).
// grid (j=10, b=256), block 256. Thread (p, i-stride-group).
// ---------------------------------------------------------------------------
__global__ __launch_bounds__(256) void k_s0() {
    const int j = blockIdx.x, b = blockIdx.y;
    const int t = threadIdx.x;
    const int p = t & 15, g = t >> 4;
    const float* base = g_hat + (size_t)(b * NJ + j) * NI * NP;
    float acc = 0.f;
    for (int i = g; i < NI; i += 16) acc += base[i * NP + p];

    __shared__ float red[256];
    red[t] = acc;
    __syncthreads();
    if (t < 128) red[t] += red[t + 128];
    __syncthreads();
    if (t < 64)  red[t] += red[t + 64];
    __syncthreads();
    if (t < 32)  red[t] += red[t + 32];
    __syncthreads();
    if (t < 16)  red[t] += red[t + 16];
    __syncthreads();

    __shared__ float sv[16];
    __shared__ float sc;
    if (t < 16) sv[t] = red[t] * 0.1f;   // c0 = 1/J exactly
    __syncthreads();
    if (t == 0) {
        float sn = 0.f;
        #pragma unroll
        for (int pp = 0; pp < 16; pp++) sn += sv[pp] * sv[pp];
        sc = sn / ((1.f + sn) * sqrtf(sn + 1e-7f));
    }
    __syncthreads();
    if (t < 16) g_out0[(b * NJ + j) * NP + t] = sv[t] * sc;
}

// ---------------------------------------------------------------------------
// K3/K5: one routing pass. logits = <outv, hat> per (j,i); softmax over j;
// s partial = sum_i c * hat over this i-chunk. Deterministic per-chunk partials.
// grid (ic=9, b=256), block 256.
// ---------------------------------------------------------------------------
__global__ __launch_bounds__(256) void k_route(int use_sum) {
    const int ic = blockIdx.x;
    const int b  = blockIdx.y;
    const int t  = threadIdx.x;

    __shared__ float cbuf[NJ * CH];   // logits -> c, 5 KB
    __shared__ float ov[NJ * NP];     // routing vector, 640 B

    const float* outv = use_sum ? g_outsum : g_out0;
    if (t < NJ * NP) ov[t] = outv[b * (NJ * NP) + t];
    __syncthreads();

    const float* hb = g_hat + (size_t)b * NJ * NI * NP;
    const int i0 = ic * CH;

    // Phase 1: logits[j][il] = dot16(hat[b,j,i0+il,:], ov[j,:])
    #pragma unroll
    for (int k = 0; k < 5; k++) {
        int idx = t + 256 * k;          // 0..1279
        int j = idx >> 7, il = idx & 127;
        const float4* h = (const float4*)(hb + (size_t)(j * NI + i0 + il) * NP);
        const float4* a = (const float4*)(ov + j * NP);
        float4 h0 = h[0], h1 = h[1], h2 = h[2], h3 = h[3];
        float4 a0 = a[0], a1 = a[1], a2 = a[2], a3 = a[3];
        float d = h0.x * a0.x + h0.y * a0.y + h0.z * a0.z + h0.w * a0.w
                + h1.x * a1.x + h1.y * a1.y + h1.z * a1.z + h1.w * a1.w
                + h2.x * a2.x + h2.y * a2.y + h2.z * a2.z + h2.w * a2.w
                + h3.x * a3.x + h3.y * a3.y + h3.z * a3.z + h3.w * a3.w;
        cbuf[idx] = d;
    }
    __syncthreads();

    // Phase 2: softmax over j for each i (thread-per-i, all in registers)
    if (t < CH) {
        float v[NJ];
        float mx = -1e30f;
        #pragma unroll
        for (int j = 0; j < NJ; j++) { v[j] = cbuf[j * CH + t]; mx = fmaxf(mx, v[j]); }
        float sum = 0.f;
        #pragma unroll
        for (int j = 0; j < NJ; j++) { v[j] = __expf(v[j] - mx); sum += v[j]; }
        float inv = 1.f / sum;
        #pragma unroll
        for (int j = 0; j < NJ; j++) cbuf[j * CH + t] = v[j] * inv;
    }
    __syncthreads();

    // Phase 3: s_partial[j,p] = sum_il c[j,il] * hat[b,j,i0+il,p]  (L1-resident)
    if (t < NJ * NP) {
        const int j = t >> 4, p = t & 15;
        const float* hc = hb + (size_t)(j * NI + i0) * NP + p;
        const float* cc = cbuf + j * CH;
        float acc = 0.f;
        #pragma unroll 8
        for (int il = 0; il < CH; il++) acc = fmaf(hc[(size_t)il * NP], cc[il], acc);
        g_spart[ic * (NB * NJ * NP) + b * (NJ * NP) + t] = acc;
    }
}

// ---------------------------------------------------------------------------
// K4: out1 = squash(sum of partials); outsum = out0 + out1  (thread per (b,j))
// ---------------------------------------------------------------------------
__global__ __launch_bounds__(256) void k_squash_mid() {
    int id = blockIdx.x * 256 + threadIdx.x;   // (b*NJ + j)
    if (id >= NB * NJ) return;
    float s[16];
    float sn = 0.f;
    #pragma unroll
    for (int p = 0; p < 16; p++) {
        float a = 0.f;
        #pragma unroll
        for (int ic = 0; ic < NCH; ic++) a += g_spart[ic * (NB * NJ * NP) + id * 16 + p];
        s[p] = a; sn += a * a;
    }
    float sc = sn / ((1.f + sn) * sqrtf(sn + 1e-7f));
    #pragma unroll
    for (int p = 0; p < 16; p++) {
        g_outsum[id * 16 + p] = s[p] * sc + g_out0[id * 16 + p];
    }
}

// ---------------------------------------------------------------------------
// K6: final = squash(sum of partials) -> d_out
// ---------------------------------------------------------------------------
__global__ __launch_bounds__(256) void k_squash_final(float* __restrict__ out) {
    int id = blockIdx.x * 256 + threadIdx.x;
    if (id >= NB * NJ) return;
    float s[16];
    float sn = 0.f;
    #pragma unroll
    for (int p = 0; p < 16; p++) {
        float a = 0.f;
        #pragma unroll
        for (int ic = 0; ic < NCH; ic++) a += g_spart[ic * (NB * NJ * NP) + id * 16 + p];
        s[p] = a; sn += a * a;
    }
    float sc = sn / ((1.f + sn) * sqrtf(sn + 1e-7f));
    #pragma unroll
    for (int p = 0; p < 16; p++) out[id * 16 + p] = s[p] * sc;
}

extern "C" void kernel_launch(void* const* d_in, const int* in_sizes, int n_in,
                              void* d_out, int out_size) {
    const float* in = (const float*)d_in[0];   // [256,1152,8]
    const float* W  = (const float*)d_in[1];   // [10,1152,16,8]
    float* out = (float*)d_out;                // [256,10,16]

    k_hat<<<dim3(18, 10, 4), 256>>>(in, W);
    k_s0<<<dim3(10, 256), 256>>>();
    k_route<<<dim3(NCH, 256), 256>>>(0);       // pass B: logits from out0
    k_squash_mid<<<10, 256>>>();
    k_route<<<dim3(NCH, 256), 256>>>(1);       // pass C: logits from out0+out1
    k_squash_final<<<10, 256>>>(out);
}

// round 2
// speedup vs baseline: 1.4729x; 1.4729x over previous
#include <cuda_runtime.h>
#include <cuda_fp16.h>
#include <math.h>

#define NB 256
#define NJ 10
#define NI 1152
#define NP 16
#define NQ 8
#define NCH 9          // i-chunks for routing kernel
#define CH 128         // i per chunk
#define JP (NJ * NP)   // 160

// Scratch (device globals — no allocation in kernel_launch).
__device__ __half g_hat[(size_t)NB * NJ * NI * NP];   // [b][j][i][p], 94.4 MB
__device__ float  g_s0f[NB * JP];                     // fused s0 accumulator
__device__ float  g_spart[NB * NCH * JP];             // [b][ic][j*16+p]
__device__ float  g_out0[NB * JP];
__device__ float  g_outsum[NB * JP];

// ---------------------------------------------------------------------------
// K1: hat[b,j,i,p] = sum_q W[j,i,p,q] * in[b,i,q]  (fp16 store)
// Fused: accumulate s0[b,j,p] = sum_i hat via warp butterfly + global REDG.
// grid (ic=18, j=10, bc=4), block 256. Thread owns (i, p-quad).
// ---------------------------------------------------------------------------
__global__ __launch_bounds__(256) void k_hat(const float* __restrict__ in,
                                             const float* __restrict__ W) {
    const int ic = blockIdx.x;          // 0..17  (64 i each)
    const int j  = blockIdx.y;          // 0..9
    const int bc = blockIdx.z;          // 0..3   (64 b each)
    const int t  = threadIdx.x;
    const int p4 = t & 3;               // which p-quad
    const int il = t >> 2;              // 0..63
    const int i  = ic * 64 + il;
    const int lane = t & 31;

    // Load this thread's 4x8 W slice once (contiguous 128 B).
    float w[4][8];
    {
        const float4* Wv = (const float4*)(W + ((size_t)(j * NI + i) * NP + p4 * 4) * NQ);
        #pragma unroll
        for (int pp = 0; pp < 4; pp++) {
            float4 a = Wv[pp * 2], c = Wv[pp * 2 + 1];
            w[pp][0] = a.x; w[pp][1] = a.y; w[pp][2] = a.z; w[pp][3] = a.w;
            w[pp][4] = c.x; w[pp][5] = c.y; w[pp][6] = c.z; w[pp][7] = c.w;
        }
    }

    __shared__ float in_s[8 * 64 * NQ];   // 16 KB

    for (int g = 0; g < 8; g++) {
        const int b0 = bc * 64 + g * 8;
        __syncthreads();
        #pragma unroll
        for (int k = 0; k < 4; k++) {
            int m   = t + 256 * k;        // float4 index 0..1023
            int bo  = m >> 7;             // 128 float4 per b
            int pos = m & 127;
            ((float4*)in_s)[m] =
                ((const float4*)(in + ((size_t)(b0 + bo) * NI + ic * 64) * NQ))[pos];
        }
        __syncthreads();
        #pragma unroll
        for (int bb = 0; bb < 8; bb++) {
            const int b = b0 + bb;
            const float* xs = in_s + (bb * 64 + il) * NQ;
            float x0 = xs[0], x1 = xs[1], x2 = xs[2], x3 = xs[3];
            float x4 = xs[4], x5 = xs[5], x6 = xs[6], x7 = xs[7];
            float r[4];
            #pragma unroll
            for (int pp = 0; pp < 4; pp++) {
                r[pp] = w[pp][0] * x0 + w[pp][1] * x1 + w[pp][2] * x2 + w[pp][3] * x3
                      + w[pp][4] * x4 + w[pp][5] * x5 + w[pp][6] * x6 + w[pp][7] * x7;
            }
            // fp16 store (8 bytes)
            union { __half2 h2[2]; uint2 u; } pk;
            pk.h2[0] = __floats2half2_rn(r[0], r[1]);
            pk.h2[1] = __floats2half2_rn(r[2], r[3]);
            *(uint2*)(g_hat + ((size_t)(b * NJ + j) * NI + i) * NP + p4 * 4) = pk.u;

            // fused s0: butterfly over il-bits within warp (lanes differ in bits 2..4)
            #pragma unroll
            for (int pp = 0; pp < 4; pp++) {
                r[pp] += __shfl_xor_sync(0xffffffffu, r[pp], 4);
                r[pp] += __shfl_xor_sync(0xffffffffu, r[pp], 8);
                r[pp] += __shfl_xor_sync(0xffffffffu, r[pp], 16);
            }
            if (lane < 4) {
                float* dst = g_s0f + (b * NJ + j) * NP + p4 * 4;
                #pragma unroll
                for (int pp = 0; pp < 4; pp++) atomicAdd(dst + pp, r[pp]);
            }
        }
    }
}

// ---------------------------------------------------------------------------
// K2: out0 = squash(0.1 * s0).  grid 256 (b), block 160 (j*16+p).
// ---------------------------------------------------------------------------
__global__ __launch_bounds__(160) void k_s0squash() {
    const int b = blockIdx.x, t = threadIdx.x;
    float s = g_s0f[b * JP + t] * 0.1f;    // c0 = 1/J exactly
    float sq = s * s;
    sq += __shfl_xor_sync(0xffffffffu, sq, 1);
    sq += __shfl_xor_sync(0xffffffffu, sq, 2);
    sq += __shfl_xor_sync(0xffffffffu, sq, 4);
    sq += __shfl_xor_sync(0xffffffffu, sq, 8);
    float sc = sq / ((1.f + sq) * sqrtf(sq + 1e-7f));
    g_out0[b * JP + t] = s * sc;
}

// ---------------------------------------------------------------------------
// K3/K5: one routing pass on fp16 hat. grid (ic=9, b=256), block 256.
// ---------------------------------------------------------------------------
__global__ __launch_bounds__(256) void k_route(int use_sum) {
    const int ic = blockIdx.x;
    const int b  = blockIdx.y;
    const int t  = threadIdx.x;

    __shared__ float cbuf[NJ * CH];   // logits -> c, 5 KB
    __shared__ float ov[JP];          // routing vector

    const float* outv = use_sum ? g_outsum : g_out0;
    if (t < JP) ov[t] = outv[b * JP + t];
    __syncthreads();

    const __half* hb = g_hat + (size_t)b * NJ * NI * NP;
    const int i0 = ic * CH;

    // Phase 1: logits[j][il] = dot16(hat[b,j,i0+il,:], ov[j,:])
    #pragma unroll
    for (int k = 0; k < 5; k++) {
        int idx = t + 256 * k;          // 0..1279
        int j = idx >> 7, il = idx & 127;
        const __half* h = hb + (size_t)(j * NI + i0 + il) * NP;
        union { uint4 u; __half2 h2[4]; } a, c;
        a.u = ((const uint4*)h)[0];
        c.u = ((const uint4*)h)[1];
        const float* av = ov + j * NP;
        float d = 0.f;
        #pragma unroll
        for (int k2 = 0; k2 < 4; k2++) {
            float2 f = __half22float2(a.h2[k2]);
            d = fmaf(f.x, av[2 * k2], d);
            d = fmaf(f.y, av[2 * k2 + 1], d);
        }
        #pragma unroll
        for (int k2 = 0; k2 < 4; k2++) {
            float2 f = __half22float2(c.h2[k2]);
            d = fmaf(f.x, av[8 + 2 * k2], d);
            d = fmaf(f.y, av[8 + 2 * k2 + 1], d);
        }
        cbuf[idx] = d;
    }
    __syncthreads();

    // Phase 2: softmax over j for each i (thread-per-i, in registers)
    if (t < CH) {
        float v[NJ];
        float mx = -1e30f;
        #pragma unroll
        for (int j = 0; j < NJ; j++) { v[j] = cbuf[j * CH + t]; mx = fmaxf(mx, v[j]); }
        float sum = 0.f;
        #pragma unroll
        for (int j = 0; j < NJ; j++) { v[j] = __expf(v[j] - mx); sum += v[j]; }
        float inv = 1.f / sum;
        #pragma unroll
        for (int j = 0; j < NJ; j++) cbuf[j * CH + t] = v[j] * inv;
    }
    __syncthreads();

    // Phase 3: s_partial[j,p] = sum_il c[j,il] * hat[..]  (L1-resident reread)
    if (t < JP) {
        const int j = t >> 4, p = t & 15;
        const __half* hc = hb + (size_t)(j * NI + i0) * NP + p;
        const float* cc = cbuf + j * CH;
        float acc = 0.f;
        #pragma unroll 8
        for (int il = 0; il < CH; il++)
            acc = fmaf(__half2float(hc[(size_t)il * NP]), cc[il], acc);
        g_spart[(b * NCH + ic) * JP + t] = acc;
    }
}

// ---------------------------------------------------------------------------
// K4: out1 = squash(sum of partials); outsum = out0 + out1.
// grid 256 (b), block 160 (j*16+p): fully coalesced partial reads.
// ---------------------------------------------------------------------------
__global__ __launch_bounds__(160) void k_squash_mid() {
    const int b = blockIdx.x, t = threadIdx.x;
    float acc = 0.f;
    #pragma unroll
    for (int ic = 0; ic < NCH; ic++) acc += g_spart[(b * NCH + ic) * JP + t];
    float sq = acc * acc;
    sq += __shfl_xor_sync(0xffffffffu, sq, 1);
    sq += __shfl_xor_sync(0xffffffffu, sq, 2);
    sq += __shfl_xor_sync(0xffffffffu, sq, 4);
    sq += __shfl_xor_sync(0xffffffffu, sq, 8);
    float sc = sq / ((1.f + sq) * sqrtf(sq + 1e-7f));
    g_outsum[b * JP + t] = acc * sc + g_out0[b * JP + t];
}

// ---------------------------------------------------------------------------
// K6: final = squash(sum of partials) -> d_out
// ---------------------------------------------------------------------------
__global__ __launch_bounds__(160) void k_squash_final(float* __restrict__ out) {
    const int b = blockIdx.x, t = threadIdx.x;
    float acc = 0.f;
    #pragma unroll
    for (int ic = 0; ic < NCH; ic++) acc += g_spart[(b * NCH + ic) * JP + t];
    float sq = acc * acc;
    sq += __shfl_xor_sync(0xffffffffu, sq, 1);
    sq += __shfl_xor_sync(0xffffffffu, sq, 2);
    sq += __shfl_xor_sync(0xffffffffu, sq, 4);
    sq += __shfl_xor_sync(0xffffffffu, sq, 8);
    float sc = sq / ((1.f + sq) * sqrtf(sq + 1e-7f));
    out[b * JP + t] = acc * sc;
}

extern "C" void kernel_launch(void* const* d_in, const int* in_sizes, int n_in,
                              void* d_out, int out_size) {
    const float* in = (const float*)d_in[0];   // [256,1152,8]
    const float* W  = (const float*)d_in[1];   // [10,1152,16,8]
    float* out = (float*)d_out;                // [256,10,16]

    void* s0p = nullptr;
    cudaGetSymbolAddress(&s0p, g_s0f);
    cudaMemsetAsync(s0p, 0, sizeof(float) * NB * JP);

    k_hat<<<dim3(18, 10, 4), 256>>>(in, W);
    k_s0squash<<<NB, 160>>>();
    k_route<<<dim3(NCH, NB), 256>>>(0);        // pass B: logits from out0
    k_squash_mid<<<NB, 160>>>();
    k_route<<<dim3(NCH, NB), 256>>>(1);        // pass C: logits from out0+out1
    k_squash_final<<<NB, 160>>>(out);
}